// round 3
// baseline (speedup 1.0000x reference)
#include <cuda_runtime.h>
#include <math.h>

#define Bsz 1024
#define Ssz 350
#define Vsz 41
#define BT 8
#define NCTA 128
#define NTHR 768

typedef unsigned long long u64;

// ---------------- persistent device scratch ----------------
__device__ float4 g_A[49152];      // Whh0 e-pair packed: [kc][gate*256 + c2*128 + j]
__device__ float4 g_B1rz[16384];   // Wih1 (r,z) pairs: [kc][c2*128 + j]
__device__ float4 g_B1n[8192];     // Wih1 n rows: [kc][j] = 4 k
__device__ float4 g_B2rz[8192];    // Whh1 (r,z)
__device__ float4 g_B2n[4096];
__device__ float4 g_C1rz[2048];    // Wih2
__device__ float4 g_C1n[1024];
__device__ float4 g_C2rz[512];     // Whh2
__device__ float4 g_C2n[256];
__device__ float  g_WprojT[1312];  // [k][j]
__device__ float  g_G0x[41 * 768]; // [v][gate][jm] -> (col jm, col jm+128) pairs
__device__ float  g_Hinit[Bsz * 416];

// ---------------- f32x2 helpers ----------------
__device__ __forceinline__ u64 fma2(u64 a, u64 b, u64 c) {
    u64 d; asm("fma.rn.f32x2 %0,%1,%2,%3;" : "=l"(d) : "l"(a), "l"(b), "l"(c)); return d;
}
__device__ __forceinline__ u64 add2(u64 a, u64 b) {
    u64 d; asm("add.rn.f32x2 %0,%1,%2;" : "=l"(d) : "l"(a), "l"(b)); return d;
}
__device__ __forceinline__ u64 pk2(float x, float y) {
    u64 d; asm("mov.b64 %0,{%1,%2};" : "=l"(d) : "f"(x), "f"(y)); return d;
}
__device__ __forceinline__ void up2(u64 a, float& x, float& y) {
    asm("mov.b64 {%0,%1}, %2;" : "=f"(x), "=f"(y) : "l"(a));
}
__device__ __forceinline__ float lo2(u64 a) { float x, y; up2(a, x, y); return x; }

__device__ __forceinline__ float sigf(float x) {
    return __fdividef(1.0f, 1.0f + __expf(-x));
}
__device__ __forceinline__ float tanh_(float x) {
    float ax = fabsf(x);
    float e = __expf(-2.0f * ax);
    float t = __fdividef(1.0f - e, 1.0f + e);
    return copysignf(t, x);
}

// ---------------- fused prep kernel (unchanged from round 2) ----------------
__global__ void k_prep(const float* __restrict__ latent, const float* __restrict__ W_emb,
                       const float* __restrict__ b_emb, const float* __restrict__ W_init,
                       const float* __restrict__ b_init, const float* __restrict__ Wih0,
                       const float* __restrict__ bih0, const float* __restrict__ Whh0,
                       const float* __restrict__ Wih1, const float* __restrict__ Whh1,
                       const float* __restrict__ Wih2, const float* __restrict__ Whh2,
                       const float* __restrict__ W_proj) {
    const int b = blockIdx.x, tid = threadIdx.x;
    const int PTH = 256;
    if (b < 128) {
        __shared__ float lat[8 * 512];
        const int b0 = b * 8;
        for (int i = tid; i < 8 * 512; i += PTH) lat[i] = latent[(size_t)b0 * 512 + i];
        __syncthreads();
        for (int c = tid; c < 416; c += PTH) {
            float acc[8];
            float bi = b_init[c];
#pragma unroll
            for (int r = 0; r < 8; r++) acc[r] = bi;
            const float* w = W_init + (size_t)c * 512;
            for (int k = 0; k < 512; k += 4) {
                float4 wv = *(const float4*)(w + k);
#pragma unroll
                for (int r = 0; r < 8; r++) {
                    acc[r] += wv.x * lat[r * 512 + k];
                    acc[r] += wv.y * lat[r * 512 + k + 1];
                    acc[r] += wv.z * lat[r * 512 + k + 2];
                    acc[r] += wv.w * lat[r * 512 + k + 3];
                }
            }
#pragma unroll
            for (int r = 0; r < 8; r++) g_Hinit[(size_t)(b0 + r) * 416 + c] = acc[r];
        }
    } else if (b < 169) {
        const int v = b - 128;
        __shared__ float emb[512];
        for (int k = tid; k < 512; k += PTH) emb[k] = W_emb[k * Vsz + v] + b_emb[k];
        __syncthreads();
        for (int j = tid; j < 768; j += PTH) {
            float acc = bih0[j];
            const float* w = Wih0 + (size_t)j * 512;
            for (int k = 0; k < 512; k += 4) {
                float4 wv = *(const float4*)(w + k);
                acc += wv.x * emb[k] + wv.y * emb[k + 1] + wv.z * emb[k + 2] + wv.w * emb[k + 3];
            }
            int g = j >> 8, rem = j & 255, e = rem >> 7, jm = rem & 127;
            g_G0x[(((size_t)v * 3 + g) * 128 + jm) * 2 + e] = acc;
        }
    } else {
        const int TOTAL = 90184;
        for (int i = (b - 169) * PTH + tid; i < TOTAL; i += 87 * PTH) {
            if (i < 49152) {
                int kc = i / 768, rem = i % 768;
                int g = rem / 256, rem2 = rem % 256, c2 = rem2 >> 7, jj = rem2 & 127;
                int k = 4 * kc + 2 * c2, row0 = g * 256 + jj, row1 = row0 + 128;
                g_A[i] = make_float4(Whh0[row0 * 256 + k], Whh0[row1 * 256 + k],
                                     Whh0[row0 * 256 + k + 1], Whh0[row1 * 256 + k + 1]);
            } else if (i < 65536) {
                int t = i - 49152;
                int kc = t / 256, c2 = (t & 255) >> 7, jj = t & 127, k = 4 * kc + 2 * c2;
                g_B1rz[t] = make_float4(Wih1[jj * 256 + k], Wih1[(128 + jj) * 256 + k],
                                        Wih1[jj * 256 + k + 1], Wih1[(128 + jj) * 256 + k + 1]);
            } else if (i < 73728) {
                int t = i - 65536;
                int kc = t >> 7, jj = t & 127;
                g_B1n[t] = *(const float4*)&Wih1[(256 + jj) * 256 + 4 * kc];
            } else if (i < 81920) {
                int t = i - 73728;
                int kc = t / 256, c2 = (t & 255) >> 7, jj = t & 127, k = 4 * kc + 2 * c2;
                g_B2rz[t] = make_float4(Whh1[jj * 128 + k], Whh1[(128 + jj) * 128 + k],
                                        Whh1[jj * 128 + k + 1], Whh1[(128 + jj) * 128 + k + 1]);
            } else if (i < 86016) {
                int t = i - 81920;
                int kc = t >> 7, jj = t & 127;
                g_B2n[t] = *(const float4*)&Whh1[(256 + jj) * 128 + 4 * kc];
            } else if (i < 88064) {
                int t = i - 86016;
                int kc = t / 64, c2 = (t & 63) >> 5, jc = t & 31, k = 4 * kc + 2 * c2;
                g_C1rz[t] = make_float4(Wih2[jc * 128 + k], Wih2[(32 + jc) * 128 + k],
                                        Wih2[jc * 128 + k + 1], Wih2[(32 + jc) * 128 + k + 1]);
            } else if (i < 89088) {
                int t = i - 88064;
                int kc = t >> 5, jc = t & 31;
                g_C1n[t] = *(const float4*)&Wih2[(64 + jc) * 128 + 4 * kc];
            } else if (i < 89600) {
                int t = i - 89088;
                int kc = t / 64, c2 = (t & 63) >> 5, jc = t & 31, k = 4 * kc + 2 * c2;
                g_C2rz[t] = make_float4(Whh2[jc * 32 + k], Whh2[(32 + jc) * 32 + k],
                                        Whh2[jc * 32 + k + 1], Whh2[(32 + jc) * 32 + k + 1]);
            } else if (i < 89856) {
                int t = i - 89600;
                int kc = t >> 5, jc = t & 31;
                g_C2n[t] = *(const float4*)&Whh2[(64 + jc) * 32 + 4 * kc];
            } else {
                int t2 = i - 89856;
#pragma unroll
                for (int c = 0; c < 4; c++) {
                    int e = t2 * 4 + c;
                    if (e < 1312) {
                        int k = e / Vsz, j = e - k * Vsz;
                        g_WprojT[e] = W_proj[j * 32 + k];
                    }
                }
            }
        }
    }
}

// ---------------- main persistent GRU kernel (gate-split, 768 threads) ----------------
__global__ __launch_bounds__(NTHR, 1)
void k_main(const int* __restrict__ tokens,
            const float* __restrict__ bhh0,
            const float* __restrict__ bih1, const float* __restrict__ bhh1,
            const float* __restrict__ bih2, const float* __restrict__ bhh2,
            const float* __restrict__ b_proj,
            float* __restrict__ out, float* __restrict__ pred) {
    __shared__ __align__(16) u64 h0d[256 * 8];
    __shared__ __align__(16) u64 h1d[128 * 8];
    __shared__ __align__(16) u64 h2d[32 * 8];
    __shared__ __align__(16) u64 cmb[2048];     // gate-partial exchange (16KB)
    __shared__ float lg[BT][44];
    __shared__ int toks_s[BT];

    const int tid = threadIdx.x;
    const int b0 = blockIdx.x * BT;
    const int g3 = tid >> 8;          // gate group 0..2
    const int tA = tid & 255;         // (jj, rh)
    const int jj = tA & 127;
    const int r0 = (tA >> 7) * 4;
    const int jc = tA & 31;
    const int rowC = tA >> 5;

    // initial state -> dup smem
    for (int idx = tid; idx < BT * 416; idx += NTHR) {
        int row = idx / 416, c = idx - row * 416;
        float v = g_Hinit[(size_t)(b0 + row) * 416 + c];
        if (c < 256)      h0d[c * 8 + row] = pk2(v, v);
        else if (c < 384) h1d[(c - 256) * 8 + row] = pk2(v, v);
        else              h2d[(c - 384) * 8 + row] = pk2(v, v);
    }

    // per-thread register biases
    const u64 bA = pk2(bhh0[g3 * 256 + jj], bhh0[g3 * 256 + 128 + jj]);  // phase A, own gate
    const u64 bB_rz = pk2(bih1[jj] + bhh1[jj], bih1[128 + jj] + bhh1[128 + jj]);
    const float b1in = bih1[256 + jj], b1hn = bhh1[256 + jj];
    const u64 bB_in = pk2(b1in, b1in);
    const u64 bB_hn = pk2(b1hn, b1hn);
    const u64 bC_rz = pk2(bih2[jc] + bhh2[jc], bih2[32 + jc] + bhh2[32 + jc]);
    const float b2in = bih2[64 + jc], b2hn = bhh2[64 + jc];
    const u64 bC_in = pk2(b2in, b2in);
    const u64 bC_hn = pk2(b2hn, b2hn);

    const u64* __restrict__ G0p = (const u64*)g_G0x;

    __syncthreads();

    for (int st = 0; st < Ssz; st++) {
        if (tid < BT) toks_s[tid] = (st == 0) ? 1 : tokens[(size_t)(b0 + tid) * Ssz + st];
        __syncthreads();

        // ======== Phase A: layer 0 — one gate per warp-group ========
        {
            u64 acc[4];
            if (g3 < 2) {
#pragma unroll
                for (int r = 0; r < 4; r++)
                    acc[r] = add2(G0p[(size_t)toks_s[r0 + r] * 384 + g3 * 128 + jj], bA);
            } else {
#pragma unroll
                for (int r = 0; r < 4; r++) acc[r] = bA;
            }
            const float4* gbase = g_A + g3 * 256 + jj;
#pragma unroll 2
            for (int kc = 0; kc < 64; kc++) {
                ulonglong2 w0 = *(const ulonglong2*)(gbase + kc * 768);
                ulonglong2 w1 = *(const ulonglong2*)(gbase + kc * 768 + 128);
                u64 W[4] = {w0.x, w0.y, w1.x, w1.y};
                u64 hv[4][4];
#pragma unroll
                for (int c = 0; c < 4; c++) {
                    ulonglong2 ha = *(const ulonglong2*)&h0d[(4 * kc + c) * 8 + r0];
                    ulonglong2 hb = *(const ulonglong2*)&h0d[(4 * kc + c) * 8 + r0 + 2];
                    hv[c][0] = ha.x; hv[c][1] = ha.y; hv[c][2] = hb.x; hv[c][3] = hb.y;
                }
#pragma unroll
                for (int c = 0; c < 4; c++)
#pragma unroll
                    for (int r = 0; r < 4; r++) acc[r] = fma2(W[c], hv[c][r], acc[r]);
            }
            if (g3 == 1) {
#pragma unroll
                for (int r = 0; r < 4; r++) cmb[r * 256 + tA] = acc[r];
            } else if (g3 == 2) {
#pragma unroll
                for (int r = 0; r < 4; r++) cmb[1024 + r * 256 + tA] = acc[r];
            }
            __syncthreads();
            if (g3 == 0) {
#pragma unroll
                for (int r = 0; r < 4; r++) {
                    u64 aZ = cmb[r * 256 + tA];
                    u64 aN = cmb[1024 + r * 256 + tA];
                    u64 gIN = G0p[(size_t)toks_s[r0 + r] * 384 + 256 + jj];
                    float r0e, r1e, z0e, z1e, n0e, n1e, i0e, i1e;
                    up2(acc[r], r0e, r1e); up2(aZ, z0e, z1e);
                    up2(aN, n0e, n1e); up2(gIN, i0e, i1e);
                    float hold0 = lo2(h0d[jj * 8 + r0 + r]);
                    float hold1 = lo2(h0d[(128 + jj) * 8 + r0 + r]);
                    float rg0 = sigf(r0e), rg1 = sigf(r1e);
                    float zg0 = sigf(z0e), zg1 = sigf(z1e);
                    float ng0 = tanh_(i0e + rg0 * n0e), ng1 = tanh_(i1e + rg1 * n1e);
                    float v0 = (1.0f - zg0) * ng0 + zg0 * hold0;
                    float v1 = (1.0f - zg1) * ng1 + zg1 * hold1;
                    h0d[jj * 8 + r0 + r] = pk2(v0, v0);
                    h0d[(128 + jj) * 8 + r0 + r] = pk2(v1, v1);
                }
            }
            __syncthreads();
        }

        // ======== Phase B: layer 1 — rz-group (g3==0) + n-group (g3==1) ========
        {
            if (g3 == 0) {
                u64 rz[4];
#pragma unroll
                for (int r = 0; r < 4; r++) rz[r] = bB_rz;
#pragma unroll 2
                for (int kc = 0; kc < 64; kc++) {
                    const float4* brz = g_B1rz + kc * 256;
                    ulonglong2 w01 = *(const ulonglong2*)(brz + jj);
                    ulonglong2 w23 = *(const ulonglong2*)(brz + 128 + jj);
                    u64 W[4] = {w01.x, w01.y, w23.x, w23.y};
                    u64 hv[4][4];
#pragma unroll
                    for (int c = 0; c < 4; c++) {
                        ulonglong2 ha = *(const ulonglong2*)&h0d[(4 * kc + c) * 8 + r0];
                        ulonglong2 hb = *(const ulonglong2*)&h0d[(4 * kc + c) * 8 + r0 + 2];
                        hv[c][0] = ha.x; hv[c][1] = ha.y; hv[c][2] = hb.x; hv[c][3] = hb.y;
                    }
#pragma unroll
                    for (int c = 0; c < 4; c++)
#pragma unroll
                        for (int r = 0; r < 4; r++) rz[r] = fma2(W[c], hv[c][r], rz[r]);
                }
#pragma unroll 2
                for (int kc = 0; kc < 32; kc++) {
                    const float4* brz = g_B2rz + kc * 256;
                    ulonglong2 w01 = *(const ulonglong2*)(brz + jj);
                    ulonglong2 w23 = *(const ulonglong2*)(brz + 128 + jj);
                    u64 W[4] = {w01.x, w01.y, w23.x, w23.y};
                    u64 hv[4][4];
#pragma unroll
                    for (int c = 0; c < 4; c++) {
                        ulonglong2 ha = *(const ulonglong2*)&h1d[(4 * kc + c) * 8 + r0];
                        ulonglong2 hb = *(const ulonglong2*)&h1d[(4 * kc + c) * 8 + r0 + 2];
                        hv[c][0] = ha.x; hv[c][1] = ha.y; hv[c][2] = hb.x; hv[c][3] = hb.y;
                    }
#pragma unroll
                    for (int c = 0; c < 4; c++)
#pragma unroll
                        for (int r = 0; r < 4; r++) rz[r] = fma2(W[c], hv[c][r], rz[r]);
                }
                __syncthreads();
#pragma unroll
                for (int r = 0; r < 4; r++) {
                    u64 iN = cmb[r * 256 + tA];
                    u64 hN = cmb[1024 + r * 256 + tA];
                    float ar, az;
                    up2(rz[r], ar, az);
                    float hold = lo2(h1d[jj * 8 + r0 + r]);
                    float rg = sigf(ar), zg = sigf(az);
                    float ng = tanh_(lo2(iN) + rg * lo2(hN));
                    float v = (1.0f - zg) * ng + zg * hold;
                    h1d[jj * 8 + r0 + r] = pk2(v, v);
                }
            } else if (g3 == 1) {
                u64 iN[4], hN[4];
#pragma unroll
                for (int r = 0; r < 4; r++) { iN[r] = bB_in; hN[r] = bB_hn; }
#pragma unroll 2
                for (int kc = 0; kc < 64; kc++) {
                    float4 wn4 = g_B1n[kc * 128 + jj];
                    u64 W[4] = {pk2(wn4.x, wn4.x), pk2(wn4.y, wn4.y),
                                pk2(wn4.z, wn4.z), pk2(wn4.w, wn4.w)};
                    u64 hv[4][4];
#pragma unroll
                    for (int c = 0; c < 4; c++) {
                        ulonglong2 ha = *(const ulonglong2*)&h0d[(4 * kc + c) * 8 + r0];
                        ulonglong2 hb = *(const ulonglong2*)&h0d[(4 * kc + c) * 8 + r0 + 2];
                        hv[c][0] = ha.x; hv[c][1] = ha.y; hv[c][2] = hb.x; hv[c][3] = hb.y;
                    }
#pragma unroll
                    for (int c = 0; c < 4; c++)
#pragma unroll
                        for (int r = 0; r < 4; r++) iN[r] = fma2(W[c], hv[c][r], iN[r]);
                }
#pragma unroll 2
                for (int kc = 0; kc < 32; kc++) {
                    float4 wn4 = g_B2n[kc * 128 + jj];
                    u64 W[4] = {pk2(wn4.x, wn4.x), pk2(wn4.y, wn4.y),
                                pk2(wn4.z, wn4.z), pk2(wn4.w, wn4.w)};
                    u64 hv[4][4];
#pragma unroll
                    for (int c = 0; c < 4; c++) {
                        ulonglong2 ha = *(const ulonglong2*)&h1d[(4 * kc + c) * 8 + r0];
                        ulonglong2 hb = *(const ulonglong2*)&h1d[(4 * kc + c) * 8 + r0 + 2];
                        hv[c][0] = ha.x; hv[c][1] = ha.y; hv[c][2] = hb.x; hv[c][3] = hb.y;
                    }
#pragma unroll
                    for (int c = 0; c < 4; c++)
#pragma unroll
                        for (int r = 0; r < 4; r++) hN[r] = fma2(W[c], hv[c][r], hN[r]);
                }
#pragma unroll
                for (int r = 0; r < 4; r++) {
                    cmb[r * 256 + tA] = iN[r];
                    cmb[1024 + r * 256 + tA] = hN[r];
                }
                __syncthreads();
            } else {
                __syncthreads();
            }
            __syncthreads();
        }

        // ======== Phase C: layer 2 — rz-group + n-group ========
        {
            if (g3 == 0) {
                u64 rz2 = bC_rz;
#pragma unroll 2
                for (int kc = 0; kc < 32; kc++) {
                    const float4* brz = g_C1rz + kc * 64;
                    ulonglong2 w01 = *(const ulonglong2*)(brz + jc);
                    ulonglong2 w23 = *(const ulonglong2*)(brz + 32 + jc);
                    u64 W[4] = {w01.x, w01.y, w23.x, w23.y};
#pragma unroll
                    for (int c = 0; c < 4; c++)
                        rz2 = fma2(W[c], h1d[(4 * kc + c) * 8 + rowC], rz2);
                }
#pragma unroll 2
                for (int kc = 0; kc < 8; kc++) {
                    const float4* brz = g_C2rz + kc * 64;
                    ulonglong2 w01 = *(const ulonglong2*)(brz + jc);
                    ulonglong2 w23 = *(const ulonglong2*)(brz + 32 + jc);
                    u64 W[4] = {w01.x, w01.y, w23.x, w23.y};
#pragma unroll
                    for (int c = 0; c < 4; c++)
                        rz2 = fma2(W[c], h2d[(4 * kc + c) * 8 + rowC], rz2);
                }
                __syncthreads();
                {
                    u64 iN2 = cmb[tA];
                    u64 hN2 = cmb[256 + tA];
                    float cr, cz;
                    up2(rz2, cr, cz);
                    float hold = lo2(h2d[jc * 8 + rowC]);
                    float rg = sigf(cr), zg = sigf(cz);
                    float ng = tanh_(lo2(iN2) + rg * lo2(hN2));
                    float v = (1.0f - zg) * ng + zg * hold;
                    h2d[jc * 8 + rowC] = pk2(v, v);
                }
            } else if (g3 == 1) {
                u64 iN2 = bC_in, hN2 = bC_hn;
#pragma unroll 2
                for (int kc = 0; kc < 32; kc++) {
                    float4 wn4 = g_C1n[kc * 32 + jc];
                    u64 W[4] = {pk2(wn4.x, wn4.x), pk2(wn4.y, wn4.y),
                                pk2(wn4.z, wn4.z), pk2(wn4.w, wn4.w)};
#pragma unroll
                    for (int c = 0; c < 4; c++)
                        iN2 = fma2(W[c], h1d[(4 * kc + c) * 8 + rowC], iN2);
                }
#pragma unroll 2
                for (int kc = 0; kc < 8; kc++) {
                    float4 wn4 = g_C2n[kc * 32 + jc];
                    u64 W[4] = {pk2(wn4.x, wn4.x), pk2(wn4.y, wn4.y),
                                pk2(wn4.z, wn4.z), pk2(wn4.w, wn4.w)};
#pragma unroll
                    for (int c = 0; c < 4; c++)
                        hN2 = fma2(W[c], h2d[(4 * kc + c) * 8 + rowC], hN2);
                }
                cmb[tA] = iN2;
                cmb[256 + tA] = hN2;
                __syncthreads();
            } else {
                __syncthreads();
            }
            __syncthreads();
        }

        // ======== Phase D: projection + argmax ========
        if (tid < BT * Vsz) {
            int row = tid / Vsz, j = tid - row * Vsz;
            float acc = b_proj[j];
#pragma unroll
            for (int k = 0; k < 32; k++)
                acc += g_WprojT[k * Vsz + j] * lo2(h2d[k * 8 + row]);
            out[((size_t)(b0 + row) * Ssz + st) * Vsz + j] = acc;
            lg[row][j] = acc;
        }
        __syncthreads();
        if (tid < BT && pred) {
            float best = lg[tid][0];
            int bi = 0;
#pragma unroll 1
            for (int j = 1; j < Vsz; j++) {
                float v = lg[tid][j];
                if (v > best) { best = v; bi = j; }
            }
            pred[(size_t)(b0 + tid) * Ssz + st] = (float)bi;
        }
        __syncthreads();
    }
}

// ---------------- launch ----------------
extern "C" void kernel_launch(void* const* d_in, const int* in_sizes, int n_in,
                              void* d_out, int out_size) {
    const float* latent  = (const float*)d_in[0];
    const int*   tokens  = (const int*)d_in[1];
    const float* W_emb   = (const float*)d_in[2];
    const float* b_emb   = (const float*)d_in[3];
    const float* W_init  = (const float*)d_in[4];
    const float* b_init  = (const float*)d_in[5];
    const float* Wih0    = (const float*)d_in[6];
    const float* Whh0    = (const float*)d_in[7];
    const float* bih0    = (const float*)d_in[8];
    const float* bhh0    = (const float*)d_in[9];
    const float* Wih1    = (const float*)d_in[10];
    const float* Whh1    = (const float*)d_in[11];
    const float* bih1    = (const float*)d_in[12];
    const float* bhh1    = (const float*)d_in[13];
    const float* Wih2    = (const float*)d_in[14];
    const float* Whh2    = (const float*)d_in[15];
    const float* bih2    = (const float*)d_in[16];
    const float* bhh2    = (const float*)d_in[17];
    const float* W_proj  = (const float*)d_in[18];
    const float* b_proj  = (const float*)d_in[19];

    float* out = (float*)d_out;
    size_t logits_elems = (size_t)Bsz * Ssz * Vsz;
    float* pred = ((size_t)out_size >= logits_elems + (size_t)Bsz * Ssz)
                      ? out + logits_elems : nullptr;

    k_prep<<<256, 256>>>(latent, W_emb, b_emb, W_init, b_init, Wih0, bih0, Whh0,
                         Wih1, Whh1, Wih2, Whh2, W_proj);
    k_main<<<NCTA, NTHR>>>(tokens, bhh0, bih1, bhh1, bih2, bhh2, b_proj, out, pred);
}